// round 12
// baseline (speedup 1.0000x reference)
#include <cuda_runtime.h>
#include <math.h>

#define BB 64
#define CC 32
#define LL 6400
#define NH 8
#define INV_PI 0.318309886183790671538f

typedef unsigned long long ull;

// ---------------- f32x2 packed-math helpers ----------------
__device__ __forceinline__ ull pack2(float lo, float hi){
    ull r; asm("mov.b64 %0,{%1,%2};" : "=l"(r) : "f"(lo), "f"(hi)); return r;
}
__device__ __forceinline__ void fma2(ull& d, ull a, ull b){
    asm("fma.rn.f32x2 %0,%1,%2,%0;" : "+l"(d) : "l"(a), "l"(b));
}
__device__ __forceinline__ float hsum2(ull v){
    float lo, hi; asm("mov.b64 {%0,%1},%2;" : "=f"(lo), "=f"(hi) : "l"(v)); return lo + hi;
}
// 32-term dot: weight row as 8x LDS.128 (ulonglong2), x as 16 packed regs
__device__ __forceinline__ float dot16q(const ulonglong2* w8, const ull* xp){
    ull a0 = 0ULL, a1 = 0ULL;
    #pragma unroll
    for(int i=0;i<8;i++){
        ulonglong2 w = w8[i];
        fma2(a0, w.x, xp[2*i]);
        fma2(a1, w.y, xp[2*i+1]);
    }
    return hsum2(a0) + hsum2(a1);
}
// dual: one weight LDS.128 stream serves two operand vectors
__device__ __forceinline__ void dot16q_dual(const ulonglong2* w8, const ull* x0, const ull* x1,
                                            float& r0, float& r1){
    ull a0=0ULL,a1=0ULL,b0=0ULL,b1=0ULL;
    #pragma unroll
    for(int i=0;i<8;i++){
        ulonglong2 w = w8[i];
        fma2(a0, w.x, x0[2*i]); fma2(a1, w.y, x0[2*i+1]);
        fma2(b0, w.x, x1[2*i]); fma2(b1, w.y, x1[2*i+1]);
    }
    r0 = hsum2(a0)+hsum2(a1);
    r1 = hsum2(b0)+hsum2(b1);
}

// ---------------- scratch ----------------
__device__ float g_q1[BB*CC*LL];
__device__ float g_v1[BB*CC*LL];
__device__ float g_v2[BB*CC*LL];
__device__ float g_f1[BB*CC*LL];
__device__ float g_f2[BB*CC*LL];
__device__ float g_part1[BB*25*256];     // [b][blk][half*128 + g*64 + combo]
__device__ float g_part2[BB*25*384];     // [b][blk][half*192 + slot]
__device__ float g_attn1[BB*NH*16];
__device__ float g_attn2[BB*NH*16];
__device__ float g_poolp[2][BB*25][64];  // [stream][block][c=sum | 32+c=max]
__device__ float g_w1[BB*CC*CC];
__device__ float g_w2[BB*CC*CC];
__device__ float g_pool[4*BB*LL];
__device__ float g_gate[BB*2*LL];

// ---------------- K1: fused qkv, adjacent-pair dual-pixel, two-phase tiles (46KB) ----------------
__global__ __launch_bounds__(128) void qkv_kernel(const float* __restrict__ rgb,
                                                  const float* __restrict__ freq,
                                                  const float* __restrict__ lw,
                                                  const float* __restrict__ xw){
    __shared__ ulonglong2 sw2[768];          // 96 rows x 8 (12KB)
    __shared__ ull tA[16][133];              // pair tiles (17KB each)
    __shared__ ull tB[16][133];
    int tid = threadIdx.x, b = blockIdx.y, S = blockIdx.z;
    const float* x = S ? freq : rgb;
    const ulonglong2* wg = (const ulonglong2*)(S ? xw : lw);
    for(int i=tid; i<768; i+=128) sw2[i] = wg[i];
    __syncthreads();
    int hf = blockIdx.x*128 + tid;           // float2 index; pixels (2hf, 2hf+1)
    const float2* xb2 = (const float2*)(x + b*CC*LL);
    ull xp0[16], xp1[16];
    #pragma unroll
    for(int c=0;c<16;c++){
        float2 a  = xb2[(2*c)*3200 + hf];
        float2 bb = xb2[(2*c+1)*3200 + hf];
        xp0[c] = pack2(a.x, bb.x);
        xp1[c] = pack2(a.y, bb.y);
    }

    int combo = tid&63, half = tid>>6;       // combo: ch*16+cd*4+ce
    int ch = combo>>4, cd = (combo>>2)&3, ce = combo&3;

    if(S==0){
        float2* qb2 = (float2*)(g_q1 + b*CC*LL);
        float2* vb2 = (float2*)(g_v1 + b*CC*LL);
        float* p1 = &g_part1[(b*25+blockIdx.x)*256];
        #pragma unroll
        for(int g=0; g<2; g++){
            #pragma unroll
            for(int hh=0; hh<4; hh++){
                int h = g*4+hh;
                float q0[4],q1[4],k0[4],k1[4],v0[4],v1[4];
                #pragma unroll
                for(int d=0;d<4;d++) dot16q_dual(sw2 + (h*4+d)*8,      xp0, xp1, q0[d], q1[d]);
                #pragma unroll
                for(int d=0;d<4;d++) dot16q_dual(sw2 + (32+h*4+d)*8,   xp0, xp1, k0[d], k1[d]);
                #pragma unroll
                for(int d=0;d<4;d++) dot16q_dual(sw2 + (64+h*4+d)*8,   xp0, xp1, v0[d], v1[d]);
                float iq0 = rsqrtf(q0[0]*q0[0]+q0[1]*q0[1]+q0[2]*q0[2]+q0[3]*q0[3]);
                float iq1 = rsqrtf(q1[0]*q1[0]+q1[1]*q1[1]+q1[2]*q1[2]+q1[3]*q1[3]);
                float ik0 = rsqrtf(k0[0]*k0[0]+k0[1]*k0[1]+k0[2]*k0[2]+k0[3]*k0[3]);
                float ik1 = rsqrtf(k1[0]*k1[0]+k1[1]*k1[1]+k1[2]*k1[2]+k1[3]*k1[3]);
                #pragma unroll
                for(int d=0;d<4;d++){
                    int j = h*4+d;
                    float2 qq; qq.x = q0[d]*iq0; qq.y = q1[d]*iq1;
                    float2 vv; vv.x = v0[d];     vv.y = v1[d];
                    qb2[j*3200 + hf] = qq;
                    vb2[j*3200 + hf] = vv;
                    tA[hh*4+d][tid] = pack2(k0[d]*ik0, k1[d]*ik1);
                    tB[hh*4+d][tid] = pack2(v0[d],     v1[d]);
                }
            }
            __syncthreads();
            {
                const ull* kr = tA[ch*4+cd] + half*64;
                const ull* vr = tB[ch*4+ce] + half*64;
                ull acc = 0ULL;
                #pragma unroll 8
                for(int i=0;i<64;i++) fma2(acc, kr[i], vr[i]);
                p1[half*128 + g*64 + combo] = hsum2(acc);
            }
            __syncthreads();
        }
    } else {
        float2* vb2 = (float2*)(g_v2 + b*CC*LL);
        float* p2 = &g_part2[(b*25+blockIdx.x)*384];
        #pragma unroll
        for(int g=0; g<2; g++){
            #pragma unroll
            for(int hh=0; hh<4; hh++){
                int h = g*4+hh;
                #pragma unroll
                for(int d=0;d<4;d++){
                    int j = h*4+d;
                    float a0,a1,b0f,b1f,c0,c1;
                    dot16q_dual(sw2 + j*8,      xp0, xp1, a0,  a1);   // q
                    dot16q_dual(sw2 + (32+j)*8, xp0, xp1, b0f, b1f);  // k
                    dot16q_dual(sw2 + (64+j)*8, xp0, xp1, c0,  c1);   // v
                    tA[hh*4+d][tid] = pack2(a0, a1);
                    tB[hh*4+d][tid] = pack2(b0f, b1f);
                    float2 vv; vv.x = c0; vv.y = c1;
                    vb2[j*3200 + hf] = vv;
                }
            }
            __syncthreads();
            {
                const ull* qr = tA[ch*4+cd] + half*64;
                const ull* kr = tB[ch*4+ce] + half*64;
                ull acc = 0ULL;
                #pragma unroll 8
                for(int i=0;i<64;i++) fma2(acc, qr[i], kr[i]);
                p2[half*192 + g*64 + combo] = hsum2(acc);
            }
            if(tid<64){
                int item = tid&31, nh = tid>>5;
                int ih = (item>>3)&3, which = (item>>2)&1, idd = item&3;
                const ull* r = (which ? tB : tA)[ih*4+idd] + nh*64;
                ull acc = 0ULL;
                #pragma unroll 8
                for(int i=0;i<64;i++) fma2(acc, r[i], r[i]);
                p2[nh*192 + 128 + g*32 + item] = hsum2(acc);
            }
            __syncthreads();
        }
    }
}

// ---------------- K2: fused reductions (y=0: lin attn, y=1: xca softmax) ----------------
__global__ __launch_bounds__(256) void red_kernel(const float* __restrict__ temp){
    int b = blockIdx.x, t = threadIdx.x;
    if(blockIdx.y==0){
        if(t<128){
            float s = 0.f;
            #pragma unroll
            for(int i=0;i<25;i++){
                int base = (b*25+i)*256;
                s += g_part1[base + t] + g_part1[base + 128 + t];
            }
            g_attn1[b*128+t] = INV_PI*s;
        }
        return;
    }
    __shared__ float red[192];
    if(t<192){
        float s=0.f;
        #pragma unroll
        for(int i=0;i<25;i++){
            int base = (b*25+i)*384;
            s += g_part2[base + t] + g_part2[base + 192 + t];
        }
        red[t]=s;
    }
    __syncthreads();
    if(t<32){
        int h = t>>2, d = t&3;
        float qn = fmaxf(sqrtf(red[128 + h*8 + d]), 1e-12f);
        float tt = temp[h];
        float vals[4]; float m = -3.4e38f;
        #pragma unroll
        for(int e=0;e<4;e++){
            float kn = fmaxf(sqrtf(red[128 + h*8 + 4 + e]), 1e-12f);
            vals[e] = red[h*16 + d*4 + e] / (qn*kn) * tt;
            m = fmaxf(m, vals[e]);
        }
        float s=0.f;
        #pragma unroll
        for(int e=0;e<4;e++){ vals[e]=expf(vals[e]-m); s+=vals[e]; }
        float inv = 1.f/s;
        #pragma unroll
        for(int e=0;e<4;e++) g_attn2[b*128 + h*16 + d*4 + e] = vals[e]*inv;
    }
}

// ---------------- K3: lin finish, 2 adjacent px/thread; buf reused svt->sf ----------------
__global__ __launch_bounds__(128) void lin_out_kernel(const float* __restrict__ dconv_w,
                                                      const float* __restrict__ projw,
                                                      const float* __restrict__ projb){
    __shared__ float attnS[128];
    __shared__ float w9[72];
    __shared__ ulonglong2 pw2[256];
    __shared__ float pb[32];
    __shared__ float buf[32][266];           // phase A: v halo tile; phase B: f tile
    __shared__ float cs[4][32], cm[4][32];
    int tid = threadIdx.x, b = blockIdx.y;
    attnS[tid] = g_attn1[b*128 + tid];
    if(tid<72) w9[tid] = dconv_w[tid];
    if(tid<32) pb[tid] = projb[tid];
    const ulonglong2* pwg = (const ulonglong2*)projw;
    for(int i=tid;i<256;i+=128) pw2[i]=pwg[i];
    int base = blockIdx.x*256;
    int half = blockIdx.x*128 + tid;         // float2 index within row
    const float* vbase = g_v1 + b*CC*LL;
    const float2* vb2 = (const float2*)vbase;
    #pragma unroll
    for(int c=0;c<32;c++){
        float2 v = vb2[c*3200 + half];
        *(float2*)&buf[c][4+2*tid] = v;
    }
    if(tid<8){
        int col = (tid<4) ? tid : (260+(tid-4));
        int hl  = (tid<4) ? (base-4+tid) : (base+256+(tid-4));
        bool ok = (hl>=0 && hl<LL);
        #pragma unroll
        for(int c=0;c<32;c++) buf[c][col] = ok ? vbase[c*LL+hl] : 0.f;
    }
    __syncthreads();
    const float2* qb2 = (const float2*)(g_q1 + b*CC*LL);
    float o0[32], o1[32];
    #pragma unroll
    for(int h=0;h<8;h++){
        float2 qv[4], vv[4];
        #pragma unroll
        for(int d=0;d<4;d++){
            qv[d] = qb2[(h*4+d)*3200 + half];
            vv[d] = *(const float2*)&buf[h*4+d][4+2*tid];
        }
        float ov0[4], ov1[4]; float s0=0.f, s1=0.f;
        #pragma unroll
        for(int e=0;e<4;e++){
            float t0 = 0.5f*vv[e].x, t1 = 0.5f*vv[e].y;
            #pragma unroll
            for(int d=0;d<4;d++){
                float a = attnS[h*16 + d*4 + e];
                t0 += qv[d].x*a; t1 += qv[d].y*a;
            }
            ov0[e]=t0; s0 += t0*t0;
            ov1[e]=t1; s1 += t1*t1;
        }
        float inv0 = rsqrtf(s0), inv1 = rsqrtf(s1);
        #pragma unroll
        for(int d=0;d<4;d++){
            float vals[10];
            #pragma unroll
            for(int j=0;j<10;j++) vals[j] = buf[h*4+d][2*tid+j];
            float a0=0.f, a1=0.f;
            #pragma unroll
            for(int t9=0;t9<9;t9++){
                float w = w9[h*9+t9];
                a0 += w*vals[t9];
                a1 += w*vals[t9+1];
            }
            o0[h*4+d] = ov0[d]*inv0 + a0;
            o1[h*4+d] = ov1[d]*inv1 + a1;
        }
    }
    __syncthreads();                          // all svt reads done; buf becomes sf
    ull op0[16], op1[16];
    #pragma unroll
    for(int cc=0;cc<16;cc++){
        op0[cc]=pack2(o0[2*cc], o0[2*cc+1]);
        op1[cc]=pack2(o1[2*cc], o1[2*cc+1]);
    }
    float2* fb2 = (float2*)(g_f1 + b*CC*LL);
    #pragma unroll
    for(int c=0;c<32;c++){
        float r0, r1;
        dot16q_dual(pw2+c*8, op0, op1, r0, r1);
        r0 += pb[c]; r1 += pb[c];
        float2 rr; rr.x=r0; rr.y=r1;
        fb2[c*3200 + half] = rr;
        *(float2*)&buf[c][2*tid] = rr;
    }
    __syncthreads();
    {
        int c = tid&31, q4 = tid>>5;
        const float* row = buf[c] + q4*64;
        float s = 0.f, m = -3.4e38f;
        #pragma unroll 8
        for(int j=0;j<64;j++){ float v=row[j]; s+=v; m=fmaxf(m,v); }
        cs[q4][c]=s; cm[q4][c]=m;
    }
    __syncthreads();
    if(tid<32){
        int blk = b*25 + blockIdx.x;
        g_poolp[0][blk][tid]    = cs[0][tid]+cs[1][tid]+cs[2][tid]+cs[3][tid];
        g_poolp[0][blk][32+tid] = fmaxf(fmaxf(cm[0][tid],cm[1][tid]),fmaxf(cm[2][tid],cm[3][tid]));
    }
}

// ---------------- K4: XCA finish, 2 adjacent px/thread ----------------
__global__ __launch_bounds__(128) void xca_out_kernel(const float* __restrict__ projw,
                                                      const float* __restrict__ projb){
    __shared__ float attnS[128];
    __shared__ ulonglong2 pw2[256];
    __shared__ float pb[32];
    __shared__ float sf[32][262];
    __shared__ float cs[4][32], cm[4][32];
    int tid = threadIdx.x, b = blockIdx.y;
    attnS[tid] = g_attn2[b*128 + tid];
    if(tid<32) pb[tid] = projb[tid];
    const ulonglong2* pwg = (const ulonglong2*)projw;
    for(int i=tid;i<256;i+=128) pw2[i]=pwg[i];
    __syncthreads();
    int half = blockIdx.x*128 + tid;
    const float2* vb2 = (const float2*)(g_v2 + b*CC*LL);
    float o0[32], o1[32];
    #pragma unroll
    for(int h=0;h<8;h++){
        float2 vv[4];
        #pragma unroll
        for(int e=0;e<4;e++) vv[e] = vb2[(h*4+e)*3200 + half];
        #pragma unroll
        for(int d=0;d<4;d++){
            float t0 = 0.f, t1 = 0.f;
            #pragma unroll
            for(int e=0;e<4;e++){
                float a = attnS[h*16 + d*4 + e];
                t0 += a*vv[e].x; t1 += a*vv[e].y;
            }
            o0[h*4+d]=t0; o1[h*4+d]=t1;
        }
    }
    ull op0[16], op1[16];
    #pragma unroll
    for(int cc=0;cc<16;cc++){
        op0[cc]=pack2(o0[2*cc], o0[2*cc+1]);
        op1[cc]=pack2(o1[2*cc], o1[2*cc+1]);
    }
    float2* fb2 = (float2*)(g_f2 + b*CC*LL);
    #pragma unroll
    for(int c=0;c<32;c++){
        float r0, r1;
        dot16q_dual(pw2+c*8, op0, op1, r0, r1);
        r0 += pb[c]; r1 += pb[c];
        float2 rr; rr.x=r0; rr.y=r1;
        fb2[c*3200 + half] = rr;
        *(float2*)&sf[c][2*tid] = rr;
    }
    __syncthreads();
    {
        int c = tid&31, q4 = tid>>5;
        const float* row = sf[c] + q4*64;
        float s = 0.f, m = -3.4e38f;
        #pragma unroll 8
        for(int j=0;j<64;j++){ float v=row[j]; s+=v; m=fmaxf(m,v); }
        cs[q4][c]=s; cm[q4][c]=m;
    }
    __syncthreads();
    if(tid<32){
        int blk = b*25 + blockIdx.x;
        g_poolp[1][blk][tid]    = cs[0][tid]+cs[1][tid]+cs[2][tid]+cs[3][tid];
        g_poolp[1][blk][32+tid] = fmaxf(fmaxf(cm[0][tid],cm[1][tid]),fmaxf(cm[2][tid],cm[3][tid]));
    }
}

// ---------------- K5: CAFM (pool reduce folded in) ----------------
__global__ __launch_bounds__(64) void cafm_kernel(
    const float* __restrict__ aw1,  const float* __restrict__ ab1,
    const float* __restrict__ mw1,  const float* __restrict__ mb1,
    const float* __restrict__ aw2,  const float* __restrict__ ab2,
    const float* __restrict__ mw2,  const float* __restrict__ mb2,
    const float* __restrict__ aw11, const float* __restrict__ ab11,
    const float* __restrict__ mw11, const float* __restrict__ mb11,
    const float* __restrict__ aw22, const float* __restrict__ ab22,
    const float* __restrict__ mw22, const float* __restrict__ mb22){
    int b = blockIdx.x, t = threadIdx.x;
    __shared__ float sa[4][32], hid[4][16], a1s[32], a2s[32];
    if(t<32){
        float s1=0.f, m1=-3.4e38f, s2=0.f, m2=-3.4e38f;
        #pragma unroll
        for(int i=0;i<25;i++){
            s1 += g_poolp[0][b*25+i][t];
            m1 = fmaxf(m1, g_poolp[0][b*25+i][32+t]);
            s2 += g_poolp[1][b*25+i][t];
            m2 = fmaxf(m2, g_poolp[1][b*25+i][32+t]);
        }
        sa[0][t] = s1 * (1.0f/LL);
        sa[1][t] = m1;
        sa[2][t] = s2 * (1.0f/LL);
        sa[3][t] = m2;
    }
    __syncthreads();
    {
        int br = t>>4, hh = t&15;
        const float* w  = (br==0)?aw1 : (br==1)?mw1 : (br==2)?aw2 : mw2;
        const float* bi = (br==0)?ab1 : (br==1)?mb1 : (br==2)?ab2 : mb2;
        float s = bi[hh];
        #pragma unroll
        for(int c=0;c<32;c++) s += sa[br][c]*w[hh*32+c];
        hid[br][hh] = fmaxf(s, 0.f);
    }
    __syncthreads();
    if(t<32){
        float s = ab11[t] + mb11[t];
        #pragma unroll
        for(int h=0;h<16;h++) s += hid[0][h]*aw11[t*16+h] + hid[1][h]*mw11[t*16+h];
        a1s[t]=s;
    } else {
        int c = t-32;
        float s = ab22[c] + mb22[c];
        #pragma unroll
        for(int h=0;h<16;h++) s += hid[2][h]*aw22[c*16+h] + hid[3][h]*mw22[c*16+h];
        a2s[c]=s;
    }
    __syncthreads();
    if(t<32){
        float a = a1s[t];
        float e[32]; float m = -3.4e38f;
        #pragma unroll
        for(int d=0;d<32;d++){ e[d]=a*a2s[d]; m=fmaxf(m,e[d]); }
        float s=0.f;
        #pragma unroll
        for(int d=0;d<32;d++){ e[d]=expf(e[d]-m); s+=e[d]; }
        float inv = 1.f/s;
        #pragma unroll
        for(int d=0;d<32;d++) g_w1[b*1024 + t*32 + d] = e[d]*inv;
    } else {
        int c = t-32;
        float a = a2s[c];
        float e[32]; float m = -3.4e38f;
        #pragma unroll
        for(int d=0;d<32;d++){ e[d]=a*a1s[d]; m=fmaxf(m,e[d]); }
        float s=0.f;
        #pragma unroll
        for(int d=0;d<32;d++){ e[d]=expf(e[d]-m); s+=e[d]; }
        float inv = 1.f/s;
        #pragma unroll
        for(int d=0;d<32;d++) g_w2[b*1024 + c*32 + d] = e[d]*inv;
    }
}

// ---------------- K6: a1f/a2f matvec + mean/max, 2 adjacent px/thread ----------------
__global__ __launch_bounds__(128) void a1f_pool_kernel(){
    __shared__ ulonglong2 w1s[256], w2s[256];
    int tid = threadIdx.x, b = blockIdx.y;
    const ulonglong2* w1g = (const ulonglong2*)(g_w1 + b*1024);
    const ulonglong2* w2g = (const ulonglong2*)(g_w2 + b*1024);
    for(int i=tid;i<256;i+=128){ w1s[i]=w1g[i]; w2s[i]=w2g[i]; }
    __syncthreads();
    int half = blockIdx.x*128 + tid;
    float2* gp = (float2*)g_pool;

    {
        const float2* fb2 = (const float2*)(g_f1 + b*CC*LL);
        ull p0[16], p1[16];
        #pragma unroll
        for(int cc=0;cc<16;cc++){
            float2 a = fb2[(2*cc)*3200 + half];
            float2 c2 = fb2[(2*cc+1)*3200 + half];
            p0[cc] = pack2(a.x, c2.x);
            p1[cc] = pack2(a.y, c2.y);
        }
        float s0=0.f, s1=0.f, m0=-3.4e38f, m1=-3.4e38f;
        #pragma unroll
        for(int c=0;c<32;c++){
            float r0, r1;
            dot16q_dual(w1s+c*8, p0, p1, r0, r1);
            s0+=r0; m0=fmaxf(m0,r0);
            s1+=r1; m1=fmaxf(m1,r1);
        }
        float2 mn; mn.x=s0*(1.f/32.f); mn.y=s1*(1.f/32.f);
        float2 mx; mx.x=m0; mx.y=m1;
        gp[(0*BB+b)*3200 + half] = mn;
        gp[(1*BB+b)*3200 + half] = mx;
    }
    {
        const float2* fb2 = (const float2*)(g_f2 + b*CC*LL);
        ull p0[16], p1[16];
        #pragma unroll
        for(int cc=0;cc<16;cc++){
            float2 a = fb2[(2*cc)*3200 + half];
            float2 c2 = fb2[(2*cc+1)*3200 + half];
            p0[cc] = pack2(a.x, c2.x);
            p1[cc] = pack2(a.y, c2.y);
        }
        float s0=0.f, s1=0.f, m0=-3.4e38f, m1=-3.4e38f;
        #pragma unroll
        for(int c=0;c<32;c++){
            float r0, r1;
            dot16q_dual(w2s+c*8, p0, p1, r0, r1);
            s0+=r0; m0=fmaxf(m0,r0);
            s1+=r1; m1=fmaxf(m1,r1);
        }
        float2 mn; mn.x=s0*(1.f/32.f); mn.y=s1*(1.f/32.f);
        float2 mx; mx.x=m0; mx.y=m1;
        gp[(2*BB+b)*3200 + half] = mn;
        gp[(3*BB+b)*3200 + half] = mx;
    }
}

// ---------------- K7: spatial gate (512 threads) ----------------
__global__ __launch_bounds__(512) void gate_kernel(const float* __restrict__ c1w,
                                                   const float* __restrict__ c1b,
                                                   const float* __restrict__ c2w,
                                                   const float* __restrict__ c2b){
    __shared__ float y1[LL];
    __shared__ float red[16];
    int t = threadIdx.x;
    int b = blockIdx.x>>1, s = blockIdx.x&1;
    const float* pm = g_pool + ((s*2+0)*BB + b)*LL;
    const float* px = g_pool + ((s*2+1)*BB + b)*LL;
    float w1c[18];
    #pragma unroll
    for(int i=0;i<18;i++) w1c[i]=c1w[i];
    float b1 = c1b[0];
    for(int l=t; l<LL; l+=512){
        int iy = l/80, ix = l%80;
        float acc = b1;
        #pragma unroll
        for(int ky=0;ky<3;ky++){
            int yy = iy+ky-1; if(yy<0||yy>=80) continue;
            #pragma unroll
            for(int kx=0;kx<3;kx++){
                int xx = ix+kx-1; if(xx<0||xx>=80) continue;
                int p = yy*80+xx;
                acc += w1c[ky*3+kx]*pm[p] + w1c[9+ky*3+kx]*px[p];
            }
        }
        y1[l] = fmaxf(acc, 0.f);
    }
    __syncthreads();
    float w2c[9];
    #pragma unroll
    for(int i=0;i<9;i++) w2c[i]=c2w[i];
    float b2 = c2b[0];
    float r[13]; float mx = -3.4e38f;
    #pragma unroll
    for(int i=0;i<13;i++){
        int l = t + i*512;
        if(l < LL){
            int iy = l/80, ix = l%80;
            float acc = b2;
            #pragma unroll
            for(int ky=0;ky<3;ky++){
                int yy = iy+ky-1; if(yy<0||yy>=80) continue;
                #pragma unroll
                for(int kx=0;kx<3;kx++){
                    int xx = ix+kx-1; if(xx<0||xx>=80) continue;
                    acc += w2c[ky*3+kx]*y1[yy*80+xx];
                }
            }
            r[i]=acc; mx=fmaxf(mx,acc);
        } else {
            r[i] = -3.4e38f;
        }
    }
    int lane = t&31, wid = t>>5;
    #pragma unroll
    for(int o=16;o>0;o>>=1) mx = fmaxf(mx, __shfl_xor_sync(0xffffffffu,mx,o));
    if(lane==0) red[wid]=mx;
    __syncthreads();
    if(t==0){ float m=red[0]; for(int w=1;w<16;w++) m=fmaxf(m,red[w]); red[0]=m; }
    __syncthreads();
    float m = red[0];
    __syncthreads();
    float sm = 0.f;
    #pragma unroll
    for(int i=0;i<13;i++){ r[i]=expf(r[i]-m); sm+=r[i]; }
    #pragma unroll
    for(int o=16;o>0;o>>=1) sm += __shfl_xor_sync(0xffffffffu,sm,o);
    if(lane==0) red[wid]=sm;
    __syncthreads();
    if(t==0){ float a=0.f; for(int w=0;w<16;w++) a+=red[w]; red[0]=a; }
    __syncthreads();
    float inv = 1.f/red[0];
    #pragma unroll
    for(int i=0;i<13;i++){
        int l = t + i*512;
        if(l < LL) g_gate[(b*2+s)*LL + l] = r[i]*inv;
    }
}

// ---------------- K8: out = f1*(1+g1) + f2*(1+g2) ----------------
__global__ __launch_bounds__(256) void final_kernel(float* __restrict__ out){
    int i = blockIdx.x*256 + threadIdx.x;
    int idx = i*4;
    int b = idx/(CC*LL);
    int l = idx%LL;
    float4 a  = ((const float4*)g_f1)[i];
    float4 c  = ((const float4*)g_f2)[i];
    float4 g1 = *(const float4*)&g_gate[(b*2+0)*LL + l];
    float4 g2 = *(const float4*)&g_gate[(b*2+1)*LL + l];
    float4 o;
    o.x = a.x*(1.f+g1.x) + c.x*(1.f+g2.x);
    o.y = a.y*(1.f+g1.y) + c.y*(1.f+g2.y);
    o.z = a.z*(1.f+g1.z) + c.z*(1.f+g2.z);
    o.w = a.w*(1.f+g1.w) + c.w*(1.f+g2.w);
    ((float4*)out)[i] = o;
}

// ---------------- launch ----------------
extern "C" void kernel_launch(void* const* d_in, const int* in_sizes, int n_in,
                              void* d_out, int out_size){
    const float* rgb       = (const float*)d_in[0];
    const float* freq      = (const float*)d_in[1];
    const float* la_qkv_w  = (const float*)d_in[2];
    const float* la_proj_w = (const float*)d_in[3];
    const float* la_proj_b = (const float*)d_in[4];
    const float* la_dconv_w= (const float*)d_in[5];
    const float* xa_qkv_w  = (const float*)d_in[6];
    const float* xa_temp   = (const float*)d_in[7];
    const float* xa_proj_w = (const float*)d_in[8];
    const float* xa_proj_b = (const float*)d_in[9];
    const float* c1s_w     = (const float*)d_in[10];
    const float* c1s_b     = (const float*)d_in[11];
    const float* c2s_w     = (const float*)d_in[12];
    const float* c2s_b     = (const float*)d_in[13];

    dim3 gqkv(25, BB, 2), g25(25, BB), gred(BB, 2);
    qkv_kernel<<<gqkv,128>>>(rgb, freq, la_qkv_w, xa_qkv_w);
    red_kernel<<<gred,256>>>(xa_temp);
    lin_out_kernel<<<g25,128>>>(la_dconv_w, la_proj_w, la_proj_b);
    xca_out_kernel<<<g25,128>>>(xa_proj_w, xa_proj_b);
    cafm_kernel<<<BB,64>>>((const float*)d_in[14],(const float*)d_in[15],
                           (const float*)d_in[16],(const float*)d_in[17],
                           (const float*)d_in[18],(const float*)d_in[19],
                           (const float*)d_in[20],(const float*)d_in[21],
                           (const float*)d_in[22],(const float*)d_in[23],
                           (const float*)d_in[24],(const float*)d_in[25],
                           (const float*)d_in[26],(const float*)d_in[27],
                           (const float*)d_in[28],(const float*)d_in[29]);
    a1f_pool_kernel<<<g25,128>>>();
    gate_kernel<<<2*BB,512>>>(c1s_w, c1s_b, c2s_w, c2s_b);
    final_kernel<<<(BB*CC*LL/4)/256,256>>>((float*)d_out);
}

// round 13
// speedup vs baseline: 1.4877x; 1.4877x over previous
#include <cuda_runtime.h>
#include <math.h>

#define BB 64
#define CC 32
#define LL 6400
#define NH 8
#define INV_PI 0.318309886183790671538f

typedef unsigned long long ull;

// ---------------- f32x2 packed-math helpers ----------------
__device__ __forceinline__ ull pack2(float lo, float hi){
    ull r; asm("mov.b64 %0,{%1,%2};" : "=l"(r) : "f"(lo), "f"(hi)); return r;
}
__device__ __forceinline__ void fma2(ull& d, ull a, ull b){
    asm("fma.rn.f32x2 %0,%1,%2,%0;" : "+l"(d) : "l"(a), "l"(b));
}
__device__ __forceinline__ float hsum2(ull v){
    float lo, hi; asm("mov.b64 {%0,%1},%2;" : "=f"(lo), "=f"(hi) : "l"(v)); return lo + hi;
}
// 32-term dot: weight row as 8x LDS.128 (ulonglong2), x as 16 packed regs
__device__ __forceinline__ float dot16q(const ulonglong2* w8, const ull* xp){
    ull a0 = 0ULL, a1 = 0ULL;
    #pragma unroll
    for(int i=0;i<8;i++){
        ulonglong2 w = w8[i];
        fma2(a0, w.x, xp[2*i]);
        fma2(a1, w.y, xp[2*i+1]);
    }
    return hsum2(a0) + hsum2(a1);
}
// dual: one weight LDS.128 stream serves two operand vectors
__device__ __forceinline__ void dot16q_dual(const ulonglong2* w8, const ull* x0, const ull* x1,
                                            float& r0, float& r1){
    ull a0=0ULL,a1=0ULL,b0=0ULL,b1=0ULL;
    #pragma unroll
    for(int i=0;i<8;i++){
        ulonglong2 w = w8[i];
        fma2(a0, w.x, x0[2*i]); fma2(a1, w.y, x0[2*i+1]);
        fma2(b0, w.x, x1[2*i]); fma2(b1, w.y, x1[2*i+1]);
    }
    r0 = hsum2(a0)+hsum2(a1);
    r1 = hsum2(b0)+hsum2(b1);
}

// ---------------- scratch ----------------
__device__ float g_q1[BB*CC*LL];
__device__ float g_v1[BB*CC*LL];
__device__ float g_v2[BB*CC*LL];
__device__ float g_f1[BB*CC*LL];
__device__ float g_f2[BB*CC*LL];
__device__ float g_part1[BB*25*256];     // [b][blk][half*128 + g*64 + combo]
__device__ float g_part2[BB*25*384];     // [b][blk][half*192 + slot]
__device__ float g_attn1[BB*NH*16];
__device__ float g_attn2[BB*NH*16];
__device__ float g_poolp[2][BB*25][64];  // [stream][block][c=sum | 32+c=max]
__device__ float g_w1[BB*CC*CC];
__device__ float g_w2[BB*CC*CC];
__device__ float g_pool[4*BB*LL];
__device__ float g_gate[BB*2*LL];

// ---------------- K1: fused qkv, dual-pixel (l0, l0+128) + two-phase pair-tile epilogue (46KB smem) ----------------
__global__ __launch_bounds__(128) void qkv_kernel(const float* __restrict__ rgb,
                                                  const float* __restrict__ freq,
                                                  const float* __restrict__ lw,
                                                  const float* __restrict__ xw){
    __shared__ ulonglong2 sw2[768];          // 96 rows x 8 (12KB)
    __shared__ ull tA[16][133];              // pair tiles (17KB each)
    __shared__ ull tB[16][133];
    int tid = threadIdx.x, b = blockIdx.y, S = blockIdx.z;
    const float* x = S ? freq : rgb;
    const ulonglong2* wg = (const ulonglong2*)(S ? xw : lw);
    for(int i=tid; i<768; i+=128) sw2[i] = wg[i];
    __syncthreads();
    int base = blockIdx.x*256;
    int l0 = base + tid;                     // second pixel at l0+128
    const float* xb = x + b*CC*LL;
    ull xp0[16], xp1[16];
    #pragma unroll
    for(int c=0;c<16;c++){
        xp0[c] = pack2(xb[(2*c)*LL+l0],     xb[(2*c+1)*LL+l0]);
        xp1[c] = pack2(xb[(2*c)*LL+l0+128], xb[(2*c+1)*LL+l0+128]);
    }

    int combo = tid&63, half = tid>>6;       // combo: ch*16+cd*4+ce
    int ch = combo>>4, cd = (combo>>2)&3, ce = combo&3;

    if(S==0){
        float* qb = g_q1 + b*CC*LL + l0;
        float* vb = g_v1 + b*CC*LL + l0;
        float* p1 = &g_part1[(b*25+blockIdx.x)*256];
        #pragma unroll
        for(int g=0; g<2; g++){
            #pragma unroll
            for(int hh=0; hh<4; hh++){
                int h = g*4+hh;
                float q0[4],q1[4],k0[4],k1[4],v0[4],v1[4];
                #pragma unroll
                for(int d=0;d<4;d++) dot16q_dual(sw2 + (h*4+d)*8,      xp0, xp1, q0[d], q1[d]);
                #pragma unroll
                for(int d=0;d<4;d++) dot16q_dual(sw2 + (32+h*4+d)*8,   xp0, xp1, k0[d], k1[d]);
                #pragma unroll
                for(int d=0;d<4;d++) dot16q_dual(sw2 + (64+h*4+d)*8,   xp0, xp1, v0[d], v1[d]);
                float iq0 = rsqrtf(q0[0]*q0[0]+q0[1]*q0[1]+q0[2]*q0[2]+q0[3]*q0[3]);
                float iq1 = rsqrtf(q1[0]*q1[0]+q1[1]*q1[1]+q1[2]*q1[2]+q1[3]*q1[3]);
                float ik0 = rsqrtf(k0[0]*k0[0]+k0[1]*k0[1]+k0[2]*k0[2]+k0[3]*k0[3]);
                float ik1 = rsqrtf(k1[0]*k1[0]+k1[1]*k1[1]+k1[2]*k1[2]+k1[3]*k1[3]);
                #pragma unroll
                for(int d=0;d<4;d++){
                    int j = h*4+d;
                    qb[j*LL]     = q0[d]*iq0;
                    qb[j*LL+128] = q1[d]*iq1;
                    vb[j*LL]     = v0[d];
                    vb[j*LL+128] = v1[d];
                    tA[hh*4+d][tid] = pack2(k0[d]*ik0, k1[d]*ik1);
                    tB[hh*4+d][tid] = pack2(v0[d],     v1[d]);
                }
            }
            __syncthreads();
            {
                const ull* kr = tA[ch*4+cd] + half*64;
                const ull* vr = tB[ch*4+ce] + half*64;
                ull acc = 0ULL;
                #pragma unroll 8
                for(int i=0;i<64;i++) fma2(acc, kr[i], vr[i]);
                p1[half*128 + g*64 + combo] = hsum2(acc);
            }
            __syncthreads();
        }
    } else {
        float* vb = g_v2 + b*CC*LL + l0;
        float* p2 = &g_part2[(b*25+blockIdx.x)*384];
        #pragma unroll
        for(int g=0; g<2; g++){
            #pragma unroll
            for(int hh=0; hh<4; hh++){
                int h = g*4+hh;
                #pragma unroll
                for(int d=0;d<4;d++){
                    int j = h*4+d;
                    float a0,a1,b0f,b1f,c0,c1;
                    dot16q_dual(sw2 + j*8,      xp0, xp1, a0,  a1);   // q
                    dot16q_dual(sw2 + (32+j)*8, xp0, xp1, b0f, b1f);  // k
                    dot16q_dual(sw2 + (64+j)*8, xp0, xp1, c0,  c1);   // v
                    tA[hh*4+d][tid] = pack2(a0, a1);
                    tB[hh*4+d][tid] = pack2(b0f, b1f);
                    vb[j*LL]     = c0;
                    vb[j*LL+128] = c1;
                }
            }
            __syncthreads();
            {
                const ull* qr = tA[ch*4+cd] + half*64;
                const ull* kr = tB[ch*4+ce] + half*64;
                ull acc = 0ULL;
                #pragma unroll 8
                for(int i=0;i<64;i++) fma2(acc, qr[i], kr[i]);
                p2[half*192 + g*64 + combo] = hsum2(acc);
            }
            if(tid<64){
                int item = tid&31, nh = tid>>5;
                int ih = (item>>3)&3, which = (item>>2)&1, idd = item&3;
                const ull* r = (which ? tB : tA)[ih*4+idd] + nh*64;
                ull acc = 0ULL;
                #pragma unroll 8
                for(int i=0;i<64;i++) fma2(acc, r[i], r[i]);
                p2[nh*192 + 128 + g*32 + item] = hsum2(acc);
            }
            __syncthreads();
        }
    }
}

// ---------------- K2: fused reductions (y=0: lin attn, y=1: xca softmax) ----------------
__global__ __launch_bounds__(256) void red_kernel(const float* __restrict__ temp){
    int b = blockIdx.x, t = threadIdx.x;
    if(blockIdx.y==0){
        if(t<128){
            float s = 0.f;
            #pragma unroll
            for(int i=0;i<25;i++){
                int base = (b*25+i)*256;
                s += g_part1[base + t] + g_part1[base + 128 + t];
            }
            g_attn1[b*128+t] = INV_PI*s;
        }
        return;
    }
    __shared__ float red[192];
    if(t<192){
        float s=0.f;
        #pragma unroll
        for(int i=0;i<25;i++){
            int base = (b*25+i)*384;
            s += g_part2[base + t] + g_part2[base + 192 + t];
        }
        red[t]=s;
    }
    __syncthreads();
    if(t<32){
        int h = t>>2, d = t&3;
        float qn = fmaxf(sqrtf(red[128 + h*8 + d]), 1e-12f);
        float tt = temp[h];
        float vals[4]; float m = -3.4e38f;
        #pragma unroll
        for(int e=0;e<4;e++){
            float kn = fmaxf(sqrtf(red[128 + h*8 + 4 + e]), 1e-12f);
            vals[e] = red[h*16 + d*4 + e] / (qn*kn) * tt;
            m = fmaxf(m, vals[e]);
        }
        float s=0.f;
        #pragma unroll
        for(int e=0;e<4;e++){ vals[e]=expf(vals[e]-m); s+=vals[e]; }
        float inv = 1.f/s;
        #pragma unroll
        for(int e=0;e<4;e++) g_attn2[b*128 + h*16 + d*4 + e] = vals[e]*inv;
    }
}

// ---------------- K3: lin finish, 2 adjacent px/thread; buf reused svt->sf ----------------
__global__ __launch_bounds__(128) void lin_out_kernel(const float* __restrict__ dconv_w,
                                                      const float* __restrict__ projw,
                                                      const float* __restrict__ projb){
    __shared__ float attnS[128];
    __shared__ float w9[72];
    __shared__ ulonglong2 pw2[256];
    __shared__ float pb[32];
    __shared__ float buf[32][266];           // phase A: v halo tile; phase B: f tile
    __shared__ float cs[4][32], cm[4][32];
    int tid = threadIdx.x, b = blockIdx.y;
    attnS[tid] = g_attn1[b*128 + tid];
    if(tid<72) w9[tid] = dconv_w[tid];
    if(tid<32) pb[tid] = projb[tid];
    const ulonglong2* pwg = (const ulonglong2*)projw;
    for(int i=tid;i<256;i+=128) pw2[i]=pwg[i];
    int base = blockIdx.x*256;
    int half = blockIdx.x*128 + tid;         // float2 index within row
    const float* vbase = g_v1 + b*CC*LL;
    const float2* vb2 = (const float2*)vbase;
    #pragma unroll
    for(int c=0;c<32;c++){
        float2 v = vb2[c*3200 + half];
        *(float2*)&buf[c][4+2*tid] = v;
    }
    if(tid<8){
        int col = (tid<4) ? tid : (260+(tid-4));
        int hl  = (tid<4) ? (base-4+tid) : (base+256+(tid-4));
        bool ok = (hl>=0 && hl<LL);
        #pragma unroll
        for(int c=0;c<32;c++) buf[c][col] = ok ? vbase[c*LL+hl] : 0.f;
    }
    __syncthreads();
    const float2* qb2 = (const float2*)(g_q1 + b*CC*LL);
    float o0[32], o1[32];
    #pragma unroll
    for(int h=0;h<8;h++){
        float2 qv[4], vv[4];
        #pragma unroll
        for(int d=0;d<4;d++){
            qv[d] = qb2[(h*4+d)*3200 + half];
            vv[d] = *(const float2*)&buf[h*4+d][4+2*tid];
        }
        float ov0[4], ov1[4]; float s0=0.f, s1=0.f;
        #pragma unroll
        for(int e=0;e<4;e++){
            float t0 = 0.5f*vv[e].x, t1 = 0.5f*vv[e].y;
            #pragma unroll
            for(int d=0;d<4;d++){
                float a = attnS[h*16 + d*4 + e];
                t0 += qv[d].x*a; t1 += qv[d].y*a;
            }
            ov0[e]=t0; s0 += t0*t0;
            ov1[e]=t1; s1 += t1*t1;
        }
        float inv0 = rsqrtf(s0), inv1 = rsqrtf(s1);
        #pragma unroll
        for(int d=0;d<4;d++){
            float vals[10];
            #pragma unroll
            for(int j=0;j<10;j++) vals[j] = buf[h*4+d][2*tid+j];
            float a0=0.f, a1=0.f;
            #pragma unroll
            for(int t9=0;t9<9;t9++){
                float w = w9[h*9+t9];
                a0 += w*vals[t9];
                a1 += w*vals[t9+1];
            }
            o0[h*4+d] = ov0[d]*inv0 + a0;
            o1[h*4+d] = ov1[d]*inv1 + a1;
        }
    }
    __syncthreads();                          // all svt reads done; buf becomes sf
    ull op0[16], op1[16];
    #pragma unroll
    for(int cc=0;cc<16;cc++){
        op0[cc]=pack2(o0[2*cc], o0[2*cc+1]);
        op1[cc]=pack2(o1[2*cc], o1[2*cc+1]);
    }
    float2* fb2 = (float2*)(g_f1 + b*CC*LL);
    #pragma unroll
    for(int c=0;c<32;c++){
        float r0, r1;
        dot16q_dual(pw2+c*8, op0, op1, r0, r1);
        r0 += pb[c]; r1 += pb[c];
        float2 rr; rr.x=r0; rr.y=r1;
        fb2[c*3200 + half] = rr;
        *(float2*)&buf[c][2*tid] = rr;
    }
    __syncthreads();
    {
        int c = tid&31, q4 = tid>>5;
        const float* row = buf[c] + q4*64;
        float s = 0.f, m = -3.4e38f;
        #pragma unroll 8
        for(int j=0;j<64;j++){ float v=row[j]; s+=v; m=fmaxf(m,v); }
        cs[q4][c]=s; cm[q4][c]=m;
    }
    __syncthreads();
    if(tid<32){
        int blk = b*25 + blockIdx.x;
        g_poolp[0][blk][tid]    = cs[0][tid]+cs[1][tid]+cs[2][tid]+cs[3][tid];
        g_poolp[0][blk][32+tid] = fmaxf(fmaxf(cm[0][tid],cm[1][tid]),fmaxf(cm[2][tid],cm[3][tid]));
    }
}

// ---------------- K4: XCA finish, 2 adjacent px/thread ----------------
__global__ __launch_bounds__(128) void xca_out_kernel(const float* __restrict__ projw,
                                                      const float* __restrict__ projb){
    __shared__ float attnS[128];
    __shared__ ulonglong2 pw2[256];
    __shared__ float pb[32];
    __shared__ float sf[32][262];
    __shared__ float cs[4][32], cm[4][32];
    int tid = threadIdx.x, b = blockIdx.y;
    attnS[tid] = g_attn2[b*128 + tid];
    if(tid<32) pb[tid] = projb[tid];
    const ulonglong2* pwg = (const ulonglong2*)projw;
    for(int i=tid;i<256;i+=128) pw2[i]=pwg[i];
    __syncthreads();
    int half = blockIdx.x*128 + tid;
    const float2* vb2 = (const float2*)(g_v2 + b*CC*LL);
    float o0[32], o1[32];
    #pragma unroll
    for(int h=0;h<8;h++){
        float2 vv[4];
        #pragma unroll
        for(int e=0;e<4;e++) vv[e] = vb2[(h*4+e)*3200 + half];
        #pragma unroll
        for(int d=0;d<4;d++){
            float t0 = 0.f, t1 = 0.f;
            #pragma unroll
            for(int e=0;e<4;e++){
                float a = attnS[h*16 + d*4 + e];
                t0 += a*vv[e].x; t1 += a*vv[e].y;
            }
            o0[h*4+d]=t0; o1[h*4+d]=t1;
        }
    }
    ull op0[16], op1[16];
    #pragma unroll
    for(int cc=0;cc<16;cc++){
        op0[cc]=pack2(o0[2*cc], o0[2*cc+1]);
        op1[cc]=pack2(o1[2*cc], o1[2*cc+1]);
    }
    float2* fb2 = (float2*)(g_f2 + b*CC*LL);
    #pragma unroll
    for(int c=0;c<32;c++){
        float r0, r1;
        dot16q_dual(pw2+c*8, op0, op1, r0, r1);
        r0 += pb[c]; r1 += pb[c];
        float2 rr; rr.x=r0; rr.y=r1;
        fb2[c*3200 + half] = rr;
        *(float2*)&sf[c][2*tid] = rr;
    }
    __syncthreads();
    {
        int c = tid&31, q4 = tid>>5;
        const float* row = sf[c] + q4*64;
        float s = 0.f, m = -3.4e38f;
        #pragma unroll 8
        for(int j=0;j<64;j++){ float v=row[j]; s+=v; m=fmaxf(m,v); }
        cs[q4][c]=s; cm[q4][c]=m;
    }
    __syncthreads();
    if(tid<32){
        int blk = b*25 + blockIdx.x;
        g_poolp[1][blk][tid]    = cs[0][tid]+cs[1][tid]+cs[2][tid]+cs[3][tid];
        g_poolp[1][blk][32+tid] = fmaxf(fmaxf(cm[0][tid],cm[1][tid]),fmaxf(cm[2][tid],cm[3][tid]));
    }
}

// ---------------- K5: CAFM (pool reduce folded in) ----------------
__global__ __launch_bounds__(64) void cafm_kernel(
    const float* __restrict__ aw1,  const float* __restrict__ ab1,
    const float* __restrict__ mw1,  const float* __restrict__ mb1,
    const float* __restrict__ aw2,  const float* __restrict__ ab2,
    const float* __restrict__ mw2,  const float* __restrict__ mb2,
    const float* __restrict__ aw11, const float* __restrict__ ab11,
    const float* __restrict__ mw11, const float* __restrict__ mb11,
    const float* __restrict__ aw22, const float* __restrict__ ab22,
    const float* __restrict__ mw22, const float* __restrict__ mb22){
    int b = blockIdx.x, t = threadIdx.x;
    __shared__ float sa[4][32], hid[4][16], a1s[32], a2s[32];
    if(t<32){
        float s1=0.f, m1=-3.4e38f, s2=0.f, m2=-3.4e38f;
        #pragma unroll
        for(int i=0;i<25;i++){
            s1 += g_poolp[0][b*25+i][t];
            m1 = fmaxf(m1, g_poolp[0][b*25+i][32+t]);
            s2 += g_poolp[1][b*25+i][t];
            m2 = fmaxf(m2, g_poolp[1][b*25+i][32+t]);
        }
        sa[0][t] = s1 * (1.0f/LL);
        sa[1][t] = m1;
        sa[2][t] = s2 * (1.0f/LL);
        sa[3][t] = m2;
    }
    __syncthreads();
    {
        int br = t>>4, hh = t&15;
        const float* w  = (br==0)?aw1 : (br==1)?mw1 : (br==2)?aw2 : mw2;
        const float* bi = (br==0)?ab1 : (br==1)?mb1 : (br==2)?ab2 : mb2;
        float s = bi[hh];
        #pragma unroll
        for(int c=0;c<32;c++) s += sa[br][c]*w[hh*32+c];
        hid[br][hh] = fmaxf(s, 0.f);
    }
    __syncthreads();
    if(t<32){
        float s = ab11[t] + mb11[t];
        #pragma unroll
        for(int h=0;h<16;h++) s += hid[0][h]*aw11[t*16+h] + hid[1][h]*mw11[t*16+h];
        a1s[t]=s;
    } else {
        int c = t-32;
        float s = ab22[c] + mb22[c];
        #pragma unroll
        for(int h=0;h<16;h++) s += hid[2][h]*aw22[c*16+h] + hid[3][h]*mw22[c*16+h];
        a2s[c]=s;
    }
    __syncthreads();
    if(t<32){
        float a = a1s[t];
        float e[32]; float m = -3.4e38f;
        #pragma unroll
        for(int d=0;d<32;d++){ e[d]=a*a2s[d]; m=fmaxf(m,e[d]); }
        float s=0.f;
        #pragma unroll
        for(int d=0;d<32;d++){ e[d]=expf(e[d]-m); s+=e[d]; }
        float inv = 1.f/s;
        #pragma unroll
        for(int d=0;d<32;d++) g_w1[b*1024 + t*32 + d] = e[d]*inv;
    } else {
        int c = t-32;
        float a = a2s[c];
        float e[32]; float m = -3.4e38f;
        #pragma unroll
        for(int d=0;d<32;d++){ e[d]=a*a1s[d]; m=fmaxf(m,e[d]); }
        float s=0.f;
        #pragma unroll
        for(int d=0;d<32;d++){ e[d]=expf(e[d]-m); s+=e[d]; }
        float inv = 1.f/s;
        #pragma unroll
        for(int d=0;d<32;d++) g_w2[b*1024 + c*32 + d] = e[d]*inv;
    }
}

// ---------------- K6: a1f/a2f matvec + mean/max, 2 adjacent px/thread ----------------
__global__ __launch_bounds__(128) void a1f_pool_kernel(){
    __shared__ ulonglong2 w1s[256], w2s[256];
    int tid = threadIdx.x, b = blockIdx.y;
    const ulonglong2* w1g = (const ulonglong2*)(g_w1 + b*1024);
    const ulonglong2* w2g = (const ulonglong2*)(g_w2 + b*1024);
    for(int i=tid;i<256;i+=128){ w1s[i]=w1g[i]; w2s[i]=w2g[i]; }
    __syncthreads();
    int half = blockIdx.x*128 + tid;
    float2* gp = (float2*)g_pool;

    {
        const float2* fb2 = (const float2*)(g_f1 + b*CC*LL);
        ull p0[16], p1[16];
        #pragma unroll
        for(int cc=0;cc<16;cc++){
            float2 a = fb2[(2*cc)*3200 + half];
            float2 c2 = fb2[(2*cc+1)*3200 + half];
            p0[cc] = pack2(a.x, c2.x);
            p1[cc] = pack2(a.y, c2.y);
        }
        float s0=0.f, s1=0.f, m0=-3.4e38f, m1=-3.4e38f;
        #pragma unroll
        for(int c=0;c<32;c++){
            float r0, r1;
            dot16q_dual(w1s+c*8, p0, p1, r0, r1);
            s0+=r0; m0=fmaxf(m0,r0);
            s1+=r1; m1=fmaxf(m1,r1);
        }
        float2 mn; mn.x=s0*(1.f/32.f); mn.y=s1*(1.f/32.f);
        float2 mx; mx.x=m0; mx.y=m1;
        gp[(0*BB+b)*3200 + half] = mn;
        gp[(1*BB+b)*3200 + half] = mx;
    }
    {
        const float2* fb2 = (const float2*)(g_f2 + b*CC*LL);
        ull p0[16], p1[16];
        #pragma unroll
        for(int cc=0;cc<16;cc++){
            float2 a = fb2[(2*cc)*3200 + half];
            float2 c2 = fb2[(2*cc+1)*3200 + half];
            p0[cc] = pack2(a.x, c2.x);
            p1[cc] = pack2(a.y, c2.y);
        }
        float s0=0.f, s1=0.f, m0=-3.4e38f, m1=-3.4e38f;
        #pragma unroll
        for(int c=0;c<32;c++){
            float r0, r1;
            dot16q_dual(w2s+c*8, p0, p1, r0, r1);
            s0+=r0; m0=fmaxf(m0,r0);
            s1+=r1; m1=fmaxf(m1,r1);
        }
        float2 mn; mn.x=s0*(1.f/32.f); mn.y=s1*(1.f/32.f);
        float2 mx; mx.x=m0; mx.y=m1;
        gp[(2*BB+b)*3200 + half] = mn;
        gp[(3*BB+b)*3200 + half] = mx;
    }
}

// ---------------- K7: spatial gate (512 threads) ----------------
__global__ __launch_bounds__(512) void gate_kernel(const float* __restrict__ c1w,
                                                   const float* __restrict__ c1b,
                                                   const float* __restrict__ c2w,
                                                   const float* __restrict__ c2b){
    __shared__ float y1[LL];
    __shared__ float red[16];
    int t = threadIdx.x;
    int b = blockIdx.x>>1, s = blockIdx.x&1;
    const float* pm = g_pool + ((s*2+0)*BB + b)*LL;
    const float* px = g_pool + ((s*2+1)*BB + b)*LL;
    float w1c[18];
    #pragma unroll
    for(int i=0;i<18;i++) w1c[i]=c1w[i];
    float b1 = c1b[0];
    for(int l=t; l<LL; l+=512){
        int iy = l/80, ix = l%80;
        float acc = b1;
        #pragma unroll
        for(int ky=0;ky<3;ky++){
            int yy = iy+ky-1; if(yy<0||yy>=80) continue;
            #pragma unroll
            for(int kx=0;kx<3;kx++){
                int xx = ix+kx-1; if(xx<0||xx>=80) continue;
                int p = yy*80+xx;
                acc += w1c[ky*3+kx]*pm[p] + w1c[9+ky*3+kx]*px[p];
            }
        }
        y1[l] = fmaxf(acc, 0.f);
    }
    __syncthreads();
    float w2c[9];
    #pragma unroll
    for(int i=0;i<9;i++) w2c[i]=c2w[i];
    float b2 = c2b[0];
    float r[13]; float mx = -3.4e38f;
    #pragma unroll
    for(int i=0;i<13;i++){
        int l = t + i*512;
        if(l < LL){
            int iy = l/80, ix = l%80;
            float acc = b2;
            #pragma unroll
            for(int ky=0;ky<3;ky++){
                int yy = iy+ky-1; if(yy<0||yy>=80) continue;
                #pragma unroll
                for(int kx=0;kx<3;kx++){
                    int xx = ix+kx-1; if(xx<0||xx>=80) continue;
                    acc += w2c[ky*3+kx]*y1[yy*80+xx];
                }
            }
            r[i]=acc; mx=fmaxf(mx,acc);
        } else {
            r[i] = -3.4e38f;
        }
    }
    int lane = t&31, wid = t>>5;
    #pragma unroll
    for(int o=16;o>0;o>>=1) mx = fmaxf(mx, __shfl_xor_sync(0xffffffffu,mx,o));
    if(lane==0) red[wid]=mx;
    __syncthreads();
    if(t==0){ float m=red[0]; for(int w=1;w<16;w++) m=fmaxf(m,red[w]); red[0]=m; }
    __syncthreads();
    float m = red[0];
    __syncthreads();
    float sm = 0.f;
    #pragma unroll
    for(int i=0;i<13;i++){
        if(t + i*512 < LL){ r[i]=expf(r[i]-m); sm+=r[i]; }
        else r[i]=0.f;
    }
    #pragma unroll
    for(int o=16;o>0;o>>=1) sm += __shfl_xor_sync(0xffffffffu,sm,o);
    if(lane==0) red[wid]=sm;
    __syncthreads();
    if(t==0){ float a=0.f; for(int w=0;w<16;w++) a+=red[w]; red[0]=a; }
    __syncthreads();
    float inv = 1.f/red[0];
    #pragma unroll
    for(int i=0;i<13;i++){
        int l = t + i*512;
        if(l < LL) g_gate[(b*2+s)*LL + l] = r[i]*inv;
    }
}

// ---------------- K8: out = f1*(1+g1) + f2*(1+g2) ----------------
__global__ __launch_bounds__(256) void final_kernel(float* __restrict__ out){
    int i = blockIdx.x*256 + threadIdx.x;
    int idx = i*4;
    int b = idx/(CC*LL);
    int l = idx%LL;
    float4 a  = ((const float4*)g_f1)[i];
    float4 c  = ((const float4*)g_f2)[i];
    float4 g1 = *(const float4*)&g_gate[(b*2+0)*LL + l];
    float4 g2 = *(const float4*)&g_gate[(b*2+1)*LL + l];
    float4 o;
    o.x = a.x*(1.f+g1.x) + c.x*(1.f+g2.x);
    o.y = a.y*(1.f+g1.y) + c.y*(1.f+g2.y);
    o.z = a.z*(1.f+g1.z) + c.z*(1.f+g2.z);
    o.w = a.w*(1.f+g1.w) + c.w*(1.f+g2.w);
    ((float4*)out)[i] = o;
}

// ---------------- launch ----------------
extern "C" void kernel_launch(void* const* d_in, const int* in_sizes, int n_in,
                              void* d_out, int out_size){
    const float* rgb       = (const float*)d_in[0];
    const float* freq      = (const float*)d_in[1];
    const float* la_qkv_w  = (const float*)d_in[2];
    const float* la_proj_w = (const float*)d_in[3];
    const float* la_proj_b = (const float*)d_in[4];
    const float* la_dconv_w= (const float*)d_in[5];
    const float* xa_qkv_w  = (const float*)d_in[6];
    const float* xa_temp   = (const float*)d_in[7];
    const float* xa_proj_w = (const float*)d_in[8];
    const float* xa_proj_b = (const float*)d_in[9];
    const float* c1s_w     = (const float*)d_in[10];
    const float* c1s_b     = (const float*)d_in[11];
    const float* c2s_w     = (const float*)d_in[12];
    const float* c2s_b     = (const float*)d_in[13];

    dim3 gqkv(25, BB, 2), g25(25, BB), gred(BB, 2);
    qkv_kernel<<<gqkv,128>>>(rgb, freq, la_qkv_w, xa_qkv_w);
    red_kernel<<<gred,256>>>(xa_temp);
    lin_out_kernel<<<g25,128>>>(la_dconv_w, la_proj_w, la_proj_b);
    xca_out_kernel<<<g25,128>>>(xa_proj_w, xa_proj_b);
    cafm_kernel<<<BB,64>>>((const float*)d_in[14],(const float*)d_in[15],
                           (const float*)d_in[16],(const float*)d_in[17],
                           (const float*)d_in[18],(const float*)d_in[19],
                           (const float*)d_in[20],(const float*)d_in[21],
                           (const float*)d_in[22],(const float*)d_in[23],
                           (const float*)d_in[24],(const float*)d_in[25],
                           (const float*)d_in[26],(const float*)d_in[27],
                           (const float*)d_in[28],(const float*)d_in[29]);
    a1f_pool_kernel<<<g25,128>>>();
    gate_kernel<<<2*BB,512>>>(c1s_w, c1s_b, c2s_w, c2s_b);
    final_kernel<<<(BB*CC*LL/4)/256,256>>>((float*)d_out);
}

// round 14
// speedup vs baseline: 1.5798x; 1.0619x over previous
#include <cuda_runtime.h>
#include <math.h>

#define BB 64
#define CC 32
#define LL 6400
#define NH 8
#define INV_PI 0.318309886183790671538f

typedef unsigned long long ull;

// ---------------- f32x2 packed-math helpers ----------------
__device__ __forceinline__ ull pack2(float lo, float hi){
    ull r; asm("mov.b64 %0,{%1,%2};" : "=l"(r) : "f"(lo), "f"(hi)); return r;
}
__device__ __forceinline__ void fma2(ull& d, ull a, ull b){
    asm("fma.rn.f32x2 %0,%1,%2,%0;" : "+l"(d) : "l"(a), "l"(b));
}
__device__ __forceinline__ float hsum2(ull v){
    float lo, hi; asm("mov.b64 {%0,%1},%2;" : "=f"(lo), "=f"(hi) : "l"(v)); return lo + hi;
}
__device__ __forceinline__ float dot16q(const ulonglong2* w8, const ull* xp){
    ull a0 = 0ULL, a1 = 0ULL;
    #pragma unroll
    for(int i=0;i<8;i++){
        ulonglong2 w = w8[i];
        fma2(a0, w.x, xp[2*i]);
        fma2(a1, w.y, xp[2*i+1]);
    }
    return hsum2(a0) + hsum2(a1);
}
__device__ __forceinline__ void dot16q_dual(const ulonglong2* w8, const ull* x0, const ull* x1,
                                            float& r0, float& r1){
    ull a0=0ULL,a1=0ULL,b0=0ULL,b1=0ULL;
    #pragma unroll
    for(int i=0;i<8;i++){
        ulonglong2 w = w8[i];
        fma2(a0, w.x, x0[2*i]); fma2(a1, w.y, x0[2*i+1]);
        fma2(b0, w.x, x1[2*i]); fma2(b1, w.y, x1[2*i+1]);
    }
    r0 = hsum2(a0)+hsum2(a1);
    r1 = hsum2(b0)+hsum2(b1);
}

// ---------------- scratch ----------------
__device__ float g_q1[BB*CC*LL];
__device__ float g_v1[BB*CC*LL];
__device__ float g_v2[BB*CC*LL];
__device__ float g_f1[BB*CC*LL];
__device__ float g_f2[BB*CC*LL];
__device__ float g_part1[BB*25*256];
__device__ float g_part2[BB*25*384];
__device__ float g_attn1[BB*NH*16];
__device__ float g_attn2[BB*NH*16];
__device__ float g_poolp[2][BB*25][64];
__device__ float g_w1[BB*CC*CC];
__device__ float g_w2[BB*CC*CC];
__device__ float g_pool[4*BB*LL];
__device__ float g_gate[BB*2*LL];

// ---------------- K1: fused qkv, dual-pixel (l0, l0+128) + two-phase pair-tile epilogue ----------------
__global__ __launch_bounds__(128) void qkv_kernel(const float* __restrict__ rgb,
                                                  const float* __restrict__ freq,
                                                  const float* __restrict__ lw,
                                                  const float* __restrict__ xw){
    __shared__ ulonglong2 sw2[768];
    __shared__ ull tA[16][133];
    __shared__ ull tB[16][133];
    int tid = threadIdx.x, b = blockIdx.y, S = blockIdx.z;
    const float* x = S ? freq : rgb;
    const ulonglong2* wg = (const ulonglong2*)(S ? xw : lw);
    for(int i=tid; i<768; i+=128) sw2[i] = wg[i];
    __syncthreads();
    int base = blockIdx.x*256;
    int l0 = base + tid;
    const float* xb = x + b*CC*LL;
    ull xp0[16], xp1[16];
    #pragma unroll
    for(int c=0;c<16;c++){
        xp0[c] = pack2(xb[(2*c)*LL+l0],     xb[(2*c+1)*LL+l0]);
        xp1[c] = pack2(xb[(2*c)*LL+l0+128], xb[(2*c+1)*LL+l0+128]);
    }

    int combo = tid&63, half = tid>>6;
    int ch = combo>>4, cd = (combo>>2)&3, ce = combo&3;

    if(S==0){
        float* qb = g_q1 + b*CC*LL + l0;
        float* vb = g_v1 + b*CC*LL + l0;
        float* p1 = &g_part1[(b*25+blockIdx.x)*256];
        #pragma unroll
        for(int g=0; g<2; g++){
            #pragma unroll
            for(int hh=0; hh<4; hh++){
                int h = g*4+hh;
                float q0[4],q1[4],k0[4],k1[4],v0[4],v1[4];
                #pragma unroll
                for(int d=0;d<4;d++) dot16q_dual(sw2 + (h*4+d)*8,      xp0, xp1, q0[d], q1[d]);
                #pragma unroll
                for(int d=0;d<4;d++) dot16q_dual(sw2 + (32+h*4+d)*8,   xp0, xp1, k0[d], k1[d]);
                #pragma unroll
                for(int d=0;d<4;d++) dot16q_dual(sw2 + (64+h*4+d)*8,   xp0, xp1, v0[d], v1[d]);
                float iq0 = rsqrtf(q0[0]*q0[0]+q0[1]*q0[1]+q0[2]*q0[2]+q0[3]*q0[3]);
                float iq1 = rsqrtf(q1[0]*q1[0]+q1[1]*q1[1]+q1[2]*q1[2]+q1[3]*q1[3]);
                float ik0 = rsqrtf(k0[0]*k0[0]+k0[1]*k0[1]+k0[2]*k0[2]+k0[3]*k0[3]);
                float ik1 = rsqrtf(k1[0]*k1[0]+k1[1]*k1[1]+k1[2]*k1[2]+k1[3]*k1[3]);
                #pragma unroll
                for(int d=0;d<4;d++){
                    int j = h*4+d;
                    qb[j*LL]     = q0[d]*iq0;
                    qb[j*LL+128] = q1[d]*iq1;
                    vb[j*LL]     = v0[d];
                    vb[j*LL+128] = v1[d];
                    tA[hh*4+d][tid] = pack2(k0[d]*ik0, k1[d]*ik1);
                    tB[hh*4+d][tid] = pack2(v0[d],     v1[d]);
                }
            }
            __syncthreads();
            {
                const ull* kr = tA[ch*4+cd] + half*64;
                const ull* vr = tB[ch*4+ce] + half*64;
                ull acc = 0ULL;
                #pragma unroll 8
                for(int i=0;i<64;i++) fma2(acc, kr[i], vr[i]);
                p1[half*128 + g*64 + combo] = hsum2(acc);
            }
            __syncthreads();
        }
    } else {
        float* vb = g_v2 + b*CC*LL + l0;
        float* p2 = &g_part2[(b*25+blockIdx.x)*384];
        #pragma unroll
        for(int g=0; g<2; g++){
            #pragma unroll
            for(int hh=0; hh<4; hh++){
                int h = g*4+hh;
                #pragma unroll
                for(int d=0;d<4;d++){
                    int j = h*4+d;
                    float a0,a1,b0f,b1f,c0,c1;
                    dot16q_dual(sw2 + j*8,      xp0, xp1, a0,  a1);
                    dot16q_dual(sw2 + (32+j)*8, xp0, xp1, b0f, b1f);
                    dot16q_dual(sw2 + (64+j)*8, xp0, xp1, c0,  c1);
                    tA[hh*4+d][tid] = pack2(a0, a1);
                    tB[hh*4+d][tid] = pack2(b0f, b1f);
                    vb[j*LL]     = c0;
                    vb[j*LL+128] = c1;
                }
            }
            __syncthreads();
            {
                const ull* qr = tA[ch*4+cd] + half*64;
                const ull* kr = tB[ch*4+ce] + half*64;
                ull acc = 0ULL;
                #pragma unroll 8
                for(int i=0;i<64;i++) fma2(acc, qr[i], kr[i]);
                p2[half*192 + g*64 + combo] = hsum2(acc);
            }
            if(tid<64){
                int item = tid&31, nh = tid>>5;
                int ih = (item>>3)&3, which = (item>>2)&1, idd = item&3;
                const ull* r = (which ? tB : tA)[ih*4+idd] + nh*64;
                ull acc = 0ULL;
                #pragma unroll 8
                for(int i=0;i<64;i++) fma2(acc, r[i], r[i]);
                p2[nh*192 + 128 + g*32 + item] = hsum2(acc);
            }
            __syncthreads();
        }
    }
}

// ---------------- K2: fused reductions ----------------
__global__ __launch_bounds__(256) void red_kernel(const float* __restrict__ temp){
    int b = blockIdx.x, t = threadIdx.x;
    if(blockIdx.y==0){
        if(t<128){
            float s = 0.f;
            #pragma unroll
            for(int i=0;i<25;i++){
                int base = (b*25+i)*256;
                s += g_part1[base + t] + g_part1[base + 128 + t];
            }
            g_attn1[b*128+t] = INV_PI*s;
        }
        return;
    }
    __shared__ float red[192];
    if(t<192){
        float s=0.f;
        #pragma unroll
        for(int i=0;i<25;i++){
            int base = (b*25+i)*384;
            s += g_part2[base + t] + g_part2[base + 192 + t];
        }
        red[t]=s;
    }
    __syncthreads();
    if(t<32){
        int h = t>>2, d = t&3;
        float qn = fmaxf(sqrtf(red[128 + h*8 + d]), 1e-12f);
        float tt = temp[h];
        float vals[4]; float m = -3.4e38f;
        #pragma unroll
        for(int e=0;e<4;e++){
            float kn = fmaxf(sqrtf(red[128 + h*8 + 4 + e]), 1e-12f);
            vals[e] = red[h*16 + d*4 + e] / (qn*kn) * tt;
            m = fmaxf(m, vals[e]);
        }
        float s=0.f;
        #pragma unroll
        for(int e=0;e<4;e++){ vals[e]=expf(vals[e]-m); s+=vals[e]; }
        float inv = 1.f/s;
        #pragma unroll
        for(int e=0;e<4;e++) g_attn2[b*128 + h*16 + d*4 + e] = vals[e]*inv;
    }
}

// ---------------- K3: merged out kernel (z=0 lin, z=1 xca), 2 adjacent px/thread ----------------
__global__ __launch_bounds__(128) void out_kernel(const float* __restrict__ dconv_w,
                                                  const float* __restrict__ lprojw,
                                                  const float* __restrict__ lprojb,
                                                  const float* __restrict__ xprojw,
                                                  const float* __restrict__ xprojb){
    __shared__ float attnS[128];
    __shared__ float w9[72];
    __shared__ ulonglong2 pw2[256];
    __shared__ float pb[32];
    __shared__ float buf[32][266];
    __shared__ float cs[4][32], cm[4][32];
    int tid = threadIdx.x, b = blockIdx.y, S = blockIdx.z;
    int half = blockIdx.x*128 + tid;

    if(S==0){
        attnS[tid] = g_attn1[b*128 + tid];
        if(tid<72) w9[tid] = dconv_w[tid];
        if(tid<32) pb[tid] = lprojb[tid];
        const ulonglong2* pwg = (const ulonglong2*)lprojw;
        for(int i=tid;i<256;i+=128) pw2[i]=pwg[i];
        int base = blockIdx.x*256;
        const float* vbase = g_v1 + b*CC*LL;
        const float2* vb2 = (const float2*)vbase;
        #pragma unroll
        for(int c=0;c<32;c++){
            float2 v = vb2[c*3200 + half];
            *(float2*)&buf[c][4+2*tid] = v;
        }
        if(tid<8){
            int col = (tid<4) ? tid : (260+(tid-4));
            int hl  = (tid<4) ? (base-4+tid) : (base+256+(tid-4));
            bool ok = (hl>=0 && hl<LL);
            #pragma unroll
            for(int c=0;c<32;c++) buf[c][col] = ok ? vbase[c*LL+hl] : 0.f;
        }
        __syncthreads();
        const float2* qb2 = (const float2*)(g_q1 + b*CC*LL);
        float o0[32], o1[32];
        #pragma unroll
        for(int h=0;h<8;h++){
            float2 qv[4], vv[4];
            #pragma unroll
            for(int d=0;d<4;d++){
                qv[d] = qb2[(h*4+d)*3200 + half];
                vv[d] = *(const float2*)&buf[h*4+d][4+2*tid];
            }
            float ov0[4], ov1[4]; float s0=0.f, s1=0.f;
            #pragma unroll
            for(int e=0;e<4;e++){
                float t0 = 0.5f*vv[e].x, t1 = 0.5f*vv[e].y;
                #pragma unroll
                for(int d=0;d<4;d++){
                    float a = attnS[h*16 + d*4 + e];
                    t0 += qv[d].x*a; t1 += qv[d].y*a;
                }
                ov0[e]=t0; s0 += t0*t0;
                ov1[e]=t1; s1 += t1*t1;
            }
            float inv0 = rsqrtf(s0), inv1 = rsqrtf(s1);
            #pragma unroll
            for(int d=0;d<4;d++){
                float vals[10];
                #pragma unroll
                for(int j=0;j<10;j++) vals[j] = buf[h*4+d][2*tid+j];
                float a0=0.f, a1=0.f;
                #pragma unroll
                for(int t9=0;t9<9;t9++){
                    float w = w9[h*9+t9];
                    a0 += w*vals[t9];
                    a1 += w*vals[t9+1];
                }
                o0[h*4+d] = ov0[d]*inv0 + a0;
                o1[h*4+d] = ov1[d]*inv1 + a1;
            }
        }
        __syncthreads();
        ull op0[16], op1[16];
        #pragma unroll
        for(int cc=0;cc<16;cc++){
            op0[cc]=pack2(o0[2*cc], o0[2*cc+1]);
            op1[cc]=pack2(o1[2*cc], o1[2*cc+1]);
        }
        float2* fb2 = (float2*)(g_f1 + b*CC*LL);
        #pragma unroll
        for(int c=0;c<32;c++){
            float r0, r1;
            dot16q_dual(pw2+c*8, op0, op1, r0, r1);
            r0 += pb[c]; r1 += pb[c];
            float2 rr; rr.x=r0; rr.y=r1;
            fb2[c*3200 + half] = rr;
            *(float2*)&buf[c][2*tid] = rr;
        }
    } else {
        attnS[tid] = g_attn2[b*128 + tid];
        if(tid<32) pb[tid] = xprojb[tid];
        const ulonglong2* pwg = (const ulonglong2*)xprojw;
        for(int i=tid;i<256;i+=128) pw2[i]=pwg[i];
        __syncthreads();
        const float2* vb2 = (const float2*)(g_v2 + b*CC*LL);
        float o0[32], o1[32];
        #pragma unroll
        for(int h=0;h<8;h++){
            float2 vv[4];
            #pragma unroll
            for(int e=0;e<4;e++) vv[e] = vb2[(h*4+e)*3200 + half];
            #pragma unroll
            for(int d=0;d<4;d++){
                float t0 = 0.f, t1 = 0.f;
                #pragma unroll
                for(int e=0;e<4;e++){
                    float a = attnS[h*16 + d*4 + e];
                    t0 += a*vv[e].x; t1 += a*vv[e].y;
                }
                o0[h*4+d]=t0; o1[h*4+d]=t1;
            }
        }
        ull op0[16], op1[16];
        #pragma unroll
        for(int cc=0;cc<16;cc++){
            op0[cc]=pack2(o0[2*cc], o0[2*cc+1]);
            op1[cc]=pack2(o1[2*cc], o1[2*cc+1]);
        }
        float2* fb2 = (float2*)(g_f2 + b*CC*LL);
        #pragma unroll
        for(int c=0;c<32;c++){
            float r0, r1;
            dot16q_dual(pw2+c*8, op0, op1, r0, r1);
            r0 += pb[c]; r1 += pb[c];
            float2 rr; rr.x=r0; rr.y=r1;
            fb2[c*3200 + half] = rr;
            *(float2*)&buf[c][2*tid] = rr;
        }
    }
    __syncthreads();
    {
        int c = tid&31, q4 = tid>>5;
        const float* row = buf[c] + q4*64;
        float s = 0.f, m = -3.4e38f;
        #pragma unroll 8
        for(int j=0;j<64;j++){ float v=row[j]; s+=v; m=fmaxf(m,v); }
        cs[q4][c]=s; cm[q4][c]=m;
    }
    __syncthreads();
    if(tid<32){
        int blk = b*25 + blockIdx.x;
        g_poolp[S][blk][tid]    = cs[0][tid]+cs[1][tid]+cs[2][tid]+cs[3][tid];
        g_poolp[S][blk][32+tid] = fmaxf(fmaxf(cm[0][tid],cm[1][tid]),fmaxf(cm[2][tid],cm[3][tid]));
    }
}

// ---------------- K5: CAFM (pool reduce folded in) ----------------
__global__ __launch_bounds__(64) void cafm_kernel(
    const float* __restrict__ aw1,  const float* __restrict__ ab1,
    const float* __restrict__ mw1,  const float* __restrict__ mb1,
    const float* __restrict__ aw2,  const float* __restrict__ ab2,
    const float* __restrict__ mw2,  const float* __restrict__ mb2,
    const float* __restrict__ aw11, const float* __restrict__ ab11,
    const float* __restrict__ mw11, const float* __restrict__ mb11,
    const float* __restrict__ aw22, const float* __restrict__ ab22,
    const float* __restrict__ mw22, const float* __restrict__ mb22){
    int b = blockIdx.x, t = threadIdx.x;
    __shared__ float sa[4][32], hid[4][16], a1s[32], a2s[32];
    if(t<32){
        float s1=0.f, m1=-3.4e38f, s2=0.f, m2=-3.4e38f;
        #pragma unroll
        for(int i=0;i<25;i++){
            s1 += g_poolp[0][b*25+i][t];
            m1 = fmaxf(m1, g_poolp[0][b*25+i][32+t]);
            s2 += g_poolp[1][b*25+i][t];
            m2 = fmaxf(m2, g_poolp[1][b*25+i][32+t]);
        }
        sa[0][t] = s1 * (1.0f/LL);
        sa[1][t] = m1;
        sa[2][t] = s2 * (1.0f/LL);
        sa[3][t] = m2;
    }
    __syncthreads();
    {
        int br = t>>4, hh = t&15;
        const float* w  = (br==0)?aw1 : (br==1)?mw1 : (br==2)?aw2 : mw2;
        const float* bi = (br==0)?ab1 : (br==1)?mb1 : (br==2)?ab2 : mb2;
        float s = bi[hh];
        #pragma unroll
        for(int c=0;c<32;c++) s += sa[br][c]*w[hh*32+c];
        hid[br][hh] = fmaxf(s, 0.f);
    }
    __syncthreads();
    if(t<32){
        float s = ab11[t] + mb11[t];
        #pragma unroll
        for(int h=0;h<16;h++) s += hid[0][h]*aw11[t*16+h] + hid[1][h]*mw11[t*16+h];
        a1s[t]=s;
    } else {
        int c = t-32;
        float s = ab22[c] + mb22[c];
        #pragma unroll
        for(int h=0;h<16;h++) s += hid[2][h]*aw22[c*16+h] + hid[3][h]*mw22[c*16+h];
        a2s[c]=s;
    }
    __syncthreads();
    if(t<32){
        float a = a1s[t];
        float e[32]; float m = -3.4e38f;
        #pragma unroll
        for(int d=0;d<32;d++){ e[d]=a*a2s[d]; m=fmaxf(m,e[d]); }
        float s=0.f;
        #pragma unroll
        for(int d=0;d<32;d++){ e[d]=expf(e[d]-m); s+=e[d]; }
        float inv = 1.f/s;
        #pragma unroll
        for(int d=0;d<32;d++) g_w1[b*1024 + t*32 + d] = e[d]*inv;
    } else {
        int c = t-32;
        float a = a2s[c];
        float e[32]; float m = -3.4e38f;
        #pragma unroll
        for(int d=0;d<32;d++){ e[d]=a*a1s[d]; m=fmaxf(m,e[d]); }
        float s=0.f;
        #pragma unroll
        for(int d=0;d<32;d++){ e[d]=expf(e[d]-m); s+=e[d]; }
        float inv = 1.f/s;
        #pragma unroll
        for(int d=0;d<32;d++) g_w2[b*1024 + c*32 + d] = e[d]*inv;
    }
}

// ---------------- K6: a1f/a2f matvec + mean/max, split by stream (z) ----------------
__global__ __launch_bounds__(128) void a1f_pool_kernel(){
    __shared__ ulonglong2 ws[256];
    int tid = threadIdx.x, b = blockIdx.y, S = blockIdx.z;
    const ulonglong2* wgg = (const ulonglong2*)((S ? g_w2 : g_w1) + b*1024);
    for(int i=tid;i<256;i+=128) ws[i]=wgg[i];
    __syncthreads();
    int half = blockIdx.x*128 + tid;
    float2* gp = (float2*)g_pool;
    const float2* fb2 = (const float2*)((S ? g_f2 : g_f1) + b*CC*LL);
    ull p0[16], p1[16];
    #pragma unroll
    for(int cc=0;cc<16;cc++){
        float2 a = fb2[(2*cc)*3200 + half];
        float2 c2 = fb2[(2*cc+1)*3200 + half];
        p0[cc] = pack2(a.x, c2.x);
        p1[cc] = pack2(a.y, c2.y);
    }
    float s0=0.f, s1=0.f, m0=-3.4e38f, m1=-3.4e38f;
    #pragma unroll
    for(int c=0;c<32;c++){
        float r0, r1;
        dot16q_dual(ws+c*8, p0, p1, r0, r1);
        s0+=r0; m0=fmaxf(m0,r0);
        s1+=r1; m1=fmaxf(m1,r1);
    }
    float2 mn; mn.x=s0*(1.f/32.f); mn.y=s1*(1.f/32.f);
    float2 mx; mx.x=m0; mx.y=m1;
    gp[((S*2+0)*BB+b)*3200 + half] = mn;
    gp[((S*2+1)*BB+b)*3200 + half] = mx;
}

// ---------------- K7: spatial gate (512 threads) ----------------
__global__ __launch_bounds__(512) void gate_kernel(const float* __restrict__ c1w,
                                                   const float* __restrict__ c1b,
                                                   const float* __restrict__ c2w,
                                                   const float* __restrict__ c2b){
    __shared__ float y1[LL];
    __shared__ float red[16];
    int t = threadIdx.x;
    int b = blockIdx.x>>1, s = blockIdx.x&1;
    const float* pm = g_pool + ((s*2+0)*BB + b)*LL;
    const float* px = g_pool + ((s*2+1)*BB + b)*LL;
    float w1c[18];
    #pragma unroll
    for(int i=0;i<18;i++) w1c[i]=c1w[i];
    float b1 = c1b[0];
    for(int l=t; l<LL; l+=512){
        int iy = l/80, ix = l%80;
        float acc = b1;
        #pragma unroll
        for(int ky=0;ky<3;ky++){
            int yy = iy+ky-1; if(yy<0||yy>=80) continue;
            #pragma unroll
            for(int kx=0;kx<3;kx++){
                int xx = ix+kx-1; if(xx<0||xx>=80) continue;
                int p = yy*80+xx;
                acc += w1c[ky*3+kx]*pm[p] + w1c[9+ky*3+kx]*px[p];
            }
        }
        y1[l] = fmaxf(acc, 0.f);
    }
    __syncthreads();
    float w2c[9];
    #pragma unroll
    for(int i=0;i<9;i++) w2c[i]=c2w[i];
    float b2 = c2b[0];
    float r[13]; float mx = -3.4e38f;
    #pragma unroll
    for(int i=0;i<13;i++){
        int l = t + i*512;
        if(l < LL){
            int iy = l/80, ix = l%80;
            float acc = b2;
            #pragma unroll
            for(int ky=0;ky<3;ky++){
                int yy = iy+ky-1; if(yy<0||yy>=80) continue;
                #pragma unroll
                for(int kx=0;kx<3;kx++){
                    int xx = ix+kx-1; if(xx<0||xx>=80) continue;
                    acc += w2c[ky*3+kx]*y1[yy*80+xx];
                }
            }
            r[i]=acc; mx=fmaxf(mx,acc);
        } else {
            r[i] = -3.4e38f;
        }
    }
    int lane = t&31, wid = t>>5;
    #pragma unroll
    for(int o=16;o>0;o>>=1) mx = fmaxf(mx, __shfl_xor_sync(0xffffffffu,mx,o));
    if(lane==0) red[wid]=mx;
    __syncthreads();
    if(t==0){ float m=red[0]; for(int w=1;w<16;w++) m=fmaxf(m,red[w]); red[0]=m; }
    __syncthreads();
    float m = red[0];
    __syncthreads();
    float sm = 0.f;
    #pragma unroll
    for(int i=0;i<13;i++){
        if(t + i*512 < LL){ r[i]=expf(r[i]-m); sm+=r[i]; }
        else r[i]=0.f;
    }
    #pragma unroll
    for(int o=16;o>0;o>>=1) sm += __shfl_xor_sync(0xffffffffu,sm,o);
    if(lane==0) red[wid]=sm;
    __syncthreads();
    if(t==0){ float a=0.f; for(int w=0;w<16;w++) a+=red[w]; red[0]=a; }
    __syncthreads();
    float inv = 1.f/red[0];
    #pragma unroll
    for(int i=0;i<13;i++){
        int l = t + i*512;
        if(l < LL) g_gate[(b*2+s)*LL + l] = r[i]*inv;
    }
}

// ---------------- K8: out = f1*(1+g1) + f2*(1+g2) ----------------
__global__ __launch_bounds__(256) void final_kernel(float* __restrict__ out){
    int i = blockIdx.x*256 + threadIdx.x;
    int idx = i*4;
    int b = idx/(CC*LL);
    int l = idx%LL;
    float4 a  = ((const float4*)g_f1)[i];
    float4 c  = ((const float4*)g_f2)[i];
    float4 g1 = *(const float4*)&g_gate[(b*2+0)*LL + l];
    float4 g2 = *(const float4*)&g_gate[(b*2+1)*LL + l];
    float4 o;
    o.x = a.x*(1.f+g1.x) + c.x*(1.f+g2.x);
    o.y = a.y*(1.f+g1.y) + c.y*(1.f+g2.y);
    o.z = a.z*(1.f+g1.z) + c.z*(1.f+g2.z);
    o.w = a.w*(1.f+g1.w) + c.w*(1.f+g2.w);
    ((float4*)out)[i] = o;
}

// ---------------- launch ----------------
extern "C" void kernel_launch(void* const* d_in, const int* in_sizes, int n_in,
                              void* d_out, int out_size){
    const float* rgb       = (const float*)d_in[0];
    const float* freq      = (const float*)d_in[1];
    const float* la_qkv_w  = (const float*)d_in[2];
    const float* la_proj_w = (const float*)d_in[3];
    const float* la_proj_b = (const float*)d_in[4];
    const float* la_dconv_w= (const float*)d_in[5];
    const float* xa_qkv_w  = (const float*)d_in[6];
    const float* xa_temp   = (const float*)d_in[7];
    const float* xa_proj_w = (const float*)d_in[8];
    const float* xa_proj_b = (const float*)d_in[9];
    const float* c1s_w     = (const float*)d_in[10];
    const float* c1s_b     = (const float*)d_in[11];
    const float* c2s_w     = (const float*)d_in[12];
    const float* c2s_b     = (const float*)d_in[13];

    dim3 gz(25, BB, 2), gred(BB, 2);
    qkv_kernel<<<gz,128>>>(rgb, freq, la_qkv_w, xa_qkv_w);
    red_kernel<<<gred,256>>>(xa_temp);
    out_kernel<<<gz,128>>>(la_dconv_w, la_proj_w, la_proj_b, xa_proj_w, xa_proj_b);
    cafm_kernel<<<BB,64>>>((const float*)d_in[14],(const float*)d_in[15],
                           (const float*)d_in[16],(const float*)d_in[17],
                           (const float*)d_in[18],(const float*)d_in[19],
                           (const float*)d_in[20],(const float*)d_in[21],
                           (const float*)d_in[22],(const float*)d_in[23],
                           (const float*)d_in[24],(const float*)d_in[25],
                           (const float*)d_in[26],(const float*)d_in[27],
                           (const float*)d_in[28],(const float*)d_in[29]);
    a1f_pool_kernel<<<gz,128>>>();
    gate_kernel<<<2*BB,512>>>(c1s_w, c1s_b, c2s_w, c2s_b);
    final_kernel<<<(BB*CC*LL/4)/256,256>>>((float*)d_out);
}